// round 5
// baseline (speedup 1.0000x reference)
#include <cuda_runtime.h>
#include <math.h>
#include <stdint.h>

// VQ_Layer: nearest-codebook quantization.
// Numerics contract: replicate the reference's fp32 rounding bit-for-bit.
//  - dot(row, code): sequential k-ascending FMA chain (cuBLAS/Eigen order)
//  - |x|^2, |e|^2: square (rounded) then sequential add (rounded), k ascending
//  - dist = (a_sq - 2*dot) single-rounded, then + b_sq rounded
//  - argmin: first index wins ties (strict < ascending scan)
//
//   inputs     [32,64,64,64] fp32  -> flat [131072, 64]
//   embeddings [1024, 64]    fp32
// Output (fp32, concatenated): quantized_st [131072*64], indices [131072],
//                              perplexity [1], vq_loss [1]

#define N_ROWS 131072
#define D 64
#define K_CODES 1024
#define TILE_K 128
#define THREADS 128
#define ROWS_PER_BLOCK 256          // 2 rows per thread
#define NUM_BLOCKS (N_ROWS / ROWS_PER_BLOCK)   // 512
#define QOFF (N_ROWS * D)           // 8388608

// Scratch (no allocations allowed): device globals.
__device__ float g_norms[K_CODES];
__device__ int   g_hist[K_CODES];
__device__ float g_partial[NUM_BLOCKS];

// Precompute code norms |e_k|^2 (square-then-add, strictly sequential in k)
// and zero the histogram (graph replays must be self-resetting).
__global__ void vq_prep_kernel(const float* __restrict__ emb) {
    int k = blockIdx.x * blockDim.x + threadIdx.x;
    if (k < K_CODES) {
        const float4* e = (const float4*)(emb + (size_t)k * D);
        float s = 0.f;
        #pragma unroll
        for (int i = 0; i < 16; i++) {
            float4 v = e[i];
            s = __fadd_rn(s, __fmul_rn(v.x, v.x));
            s = __fadd_rn(s, __fmul_rn(v.y, v.y));
            s = __fadd_rn(s, __fmul_rn(v.z, v.z));
            s = __fadd_rn(s, __fmul_rn(v.w, v.w));
        }
        g_norms[k] = s;
        g_hist[k]  = 0;
    }
}

__global__ __launch_bounds__(THREADS) void vq_main_kernel(
    const float* __restrict__ inp,
    const float* __restrict__ emb,
    float* __restrict__ out)
{
    __shared__ __align__(16) float sh_e[TILE_K * D];   // 32 KB code tile
    __shared__ float sh_norm[TILE_K];
    __shared__ float sh_red[THREADS];

    const int tid = threadIdx.x;
    const int r0 = blockIdx.x * ROWS_PER_BLOCK + tid;
    const int r1 = r0 + THREADS;

    // Load both rows into registers (float4 vector loads).
    float4 x0[16], x1[16];
    {
        const float4* p0 = (const float4*)(inp + (size_t)r0 * D);
        const float4* p1 = (const float4*)(inp + (size_t)r1 * D);
        #pragma unroll
        for (int i = 0; i < 16; i++) { x0[i] = p0[i]; x1[i] = p1[i]; }
    }

    // |x|^2 per row: square (rounded) then add (rounded), sequential k order
    // -- matches jnp.sum(flat*flat, axis=1) elementwise-square + ordered sum.
    float asq0, asq1;
    {
        float s = 0.f;
        #pragma unroll
        for (int i = 0; i < 16; i++) {
            float4 v = x0[i];
            s = __fadd_rn(s, __fmul_rn(v.x, v.x));
            s = __fadd_rn(s, __fmul_rn(v.y, v.y));
            s = __fadd_rn(s, __fmul_rn(v.z, v.z));
            s = __fadd_rn(s, __fmul_rn(v.w, v.w));
        }
        asq0 = s;
    }
    {
        float s = 0.f;
        #pragma unroll
        for (int i = 0; i < 16; i++) {
            float4 v = x1[i];
            s = __fadd_rn(s, __fmul_rn(v.x, v.x));
            s = __fadd_rn(s, __fmul_rn(v.y, v.y));
            s = __fadd_rn(s, __fmul_rn(v.z, v.z));
            s = __fadd_rn(s, __fmul_rn(v.w, v.w));
        }
        asq1 = s;
    }

    float best0 = 3.402823466e38f, best1 = 3.402823466e38f;
    int bi0 = 0, bi1 = 0;

    for (int t = 0; t < K_CODES; t += TILE_K) {
        __syncthreads();
        // Cooperative, fully coalesced tile load: 2048 float4.
        const float4* gsrc = (const float4*)(emb + (size_t)t * D);
        float4* sdst = (float4*)sh_e;
        #pragma unroll
        for (int i = 0; i < 16; i++)
            sdst[tid + i * THREADS] = gsrc[tid + i * THREADS];
        sh_norm[tid] = g_norms[t + tid];    // TILE_K == THREADS
        __syncthreads();

        #pragma unroll 2
        for (int c = 0; c < TILE_K; c++) {
            const float4* ep = (const float4*)(sh_e + c * D);
            // Strictly sequential k-ascending FMA chains (one per row):
            // matches cuBLAS / Eigen gemm accumulation order bit-for-bit.
            float dot0 = 0.f, dot1 = 0.f;
            #pragma unroll
            for (int j = 0; j < 16; j++) {
                float4 e = ep[j];       // LDS.128, uniform addr = broadcast
                float4 a = x0[j];
                dot0 = __fmaf_rn(a.x, e.x, dot0);
                dot0 = __fmaf_rn(a.y, e.y, dot0);
                dot0 = __fmaf_rn(a.z, e.z, dot0);
                dot0 = __fmaf_rn(a.w, e.w, dot0);
                float4 b = x1[j];
                dot1 = __fmaf_rn(b.x, e.x, dot1);
                dot1 = __fmaf_rn(b.y, e.y, dot1);
                dot1 = __fmaf_rn(b.z, e.z, dot1);
                dot1 = __fmaf_rn(b.w, e.w, dot1);
            }
            const float bn = sh_norm[c];
            {
                // round(asq - 2*dot)  [== ref's a_sq - ab], then + b_sq.
                float dist = __fadd_rn(__fmaf_rn(-2.f, dot0, asq0), bn);
                if (dist < best0) { best0 = dist; bi0 = t + c; }
            }
            {
                float dist = __fadd_rn(__fmaf_rn(-2.f, dot1, asq1), bn);
                if (dist < best1) { best1 = dist; bi1 = t + c; }
            }
        }
    }

    // Epilogue: gather code row, write quantized + index, accumulate loss.
    float ls = 0.f;
    {
        const float4* eq = (const float4*)(emb + (size_t)bi0 * D);
        float4* qo = (float4*)(out + (size_t)r0 * D);
        #pragma unroll
        for (int i = 0; i < 16; i++) {
            float4 q = eq[i];
            float4 v = x0[i];
            float da = v.x - q.x, db = v.y - q.y, dc = v.z - q.z, dd = v.w - q.w;
            ls = fmaf(da, da, ls); ls = fmaf(db, db, ls);
            ls = fmaf(dc, dc, ls); ls = fmaf(dd, dd, ls);
            qo[i] = q;
        }
        out[QOFF + r0] = (float)bi0;
        atomicAdd(&g_hist[bi0], 1);
    }
    {
        const float4* eq = (const float4*)(emb + (size_t)bi1 * D);
        float4* qo = (float4*)(out + (size_t)r1 * D);
        #pragma unroll
        for (int i = 0; i < 16; i++) {
            float4 q = eq[i];
            float4 v = x1[i];
            float da = v.x - q.x, db = v.y - q.y, dc = v.z - q.z, dd = v.w - q.w;
            ls = fmaf(da, da, ls); ls = fmaf(db, db, ls);
            ls = fmaf(dc, dc, ls); ls = fmaf(dd, dd, ls);
            qo[i] = q;
        }
        out[QOFF + r1] = (float)bi1;
        atomicAdd(&g_hist[bi1], 1);
    }

    // Deterministic per-block loss partial.
    sh_red[tid] = ls;
    __syncthreads();
    for (int s = THREADS / 2; s > 0; s >>= 1) {
        if (tid < s) sh_red[tid] += sh_red[tid + s];
        __syncthreads();
    }
    if (tid == 0) g_partial[blockIdx.x] = sh_red[0];
}

// Perplexity + vq_loss (single block; deterministic tree reductions).
__global__ void vq_final_kernel(float* __restrict__ out) {
    __shared__ float sh[1024];
    const int t = threadIdx.x;

    float p = (float)g_hist[t] * (1.0f / (float)N_ROWS);
    sh[t] = p * logf(p + 1e-10f);
    __syncthreads();
    for (int s = 512; s > 0; s >>= 1) {
        if (t < s) sh[t] += sh[t + s];
        __syncthreads();
    }
    float ent = sh[0];
    __syncthreads();

    sh[t] = (t < NUM_BLOCKS) ? g_partial[t] : 0.f;
    __syncthreads();
    for (int s = 512; s > 0; s >>= 1) {
        if (t < s) sh[t] += sh[t + s];
        __syncthreads();
    }

    if (t == 0) {
        float m = sh[0] / (float)((size_t)N_ROWS * D);
        out[QOFF + N_ROWS]     = expf(-ent);       // perplexity
        out[QOFF + N_ROWS + 1] = m + 0.25f * m;    // commitment + beta*codebook
    }
}

extern "C" void kernel_launch(void* const* d_in, const int* in_sizes, int n_in,
                              void* d_out, int out_size) {
    const float* inp = (const float*)d_in[0];   // [131072, 64]
    const float* emb = (const float*)d_in[1];   // [1024, 64]
    float* out = (float*)d_out;

    vq_prep_kernel<<<4, 256>>>(emb);
    vq_main_kernel<<<NUM_BLOCKS, THREADS>>>(inp, emb, out);
    vq_final_kernel<<<1, 1024>>>(out);
}